// round 4
// baseline (speedup 1.0000x reference)
#include <cuda_runtime.h>

#define NVOX 500000
#define CH 8
#define KT 27
#define TPB 128
#define RPT 4                      // rows per thread
#define RPB (TPB * RPT)            // 512 rows per block

// Static scratch (allocation-free): activations ping-pong + tap-major nbr maps.
__device__ float g_bufA[NVOX * CH];                 // 16 MB
__device__ float g_bufB[NVOX * CH];                 // 16 MB
__device__ int   g_nbrT0[KT * NVOX];                // 54 MB, nbrT[k*N + n]
__device__ int   g_nbrT1[KT * NVOX];                // 54 MB

__device__ __forceinline__ void ffma2(unsigned long long& d,
                                      unsigned long long a,
                                      unsigned long long b) {
    asm volatile("fma.rn.f32x2 %0, %1, %2, %0;" : "+l"(d) : "l"(a), "l"(b));
}

__device__ __forceinline__ unsigned long long pack2(float x) {
    unsigned long long r;
    unsigned int xb = __float_as_uint(x);
    asm("mov.b64 %0, {%1, %1};" : "=l"(r) : "r"(xb));
    return r;
}

// Transpose nbr [N][27] -> nbrT [27][N]. Coalesced load via smem, coalesced store.
__global__ void __launch_bounds__(256)
transpose_nbr(const int* __restrict__ nbr, int* __restrict__ nbrT) {
    __shared__ int s[256 * KT];
    const int base = blockIdx.x * 256;
    const int rows = min(256, NVOX - base);
    const int nvec = (rows * KT) >> 2;               // rows*27 %4==0 for 256 and 32
    const int4* src = (const int4*)(nbr + (long long)base * KT);
    for (int i = threadIdx.x; i < nvec; i += 256) ((int4*)s)[i] = src[i];
    __syncthreads();
    const int t = threadIdx.x;
    if (t < rows) {
#pragma unroll
        for (int k = 0; k < KT; k++)
            nbrT[k * NVOX + base + t] = s[t * KT + k];
    }
}

template <bool RELU, bool RES>
__global__ void __launch_bounds__(TPB, 5)
spconv_kernel(const float4* __restrict__ x,      // [NVOX][2] float4
              const int*    __restrict__ nbrT,   // [27][NVOX]
              const float*  __restrict__ w,      // [27][8][8]
              const float4* __restrict__ resid,  // [NVOX][2] or null
              float4*       __restrict__ out)    // [NVOX][2]
{
    // Weights as f32x2 pairs: sw[k*32 + cin*4 + p] = (w[k][cin][2p], w[k][cin][2p+1])
    __shared__ __align__(16) unsigned long long sw[KT * 32];   // 6912 B
    {
        const unsigned long long* w2 = (const unsigned long long*)w;
        for (int i = threadIdx.x; i < KT * 32; i += TPB) sw[i] = w2[i];
    }
    __syncthreads();

    const int t = threadIdx.x;
    const int base = blockIdx.x * RPB;
    int r[RPT]; bool ok[RPT];
#pragma unroll
    for (int s = 0; s < RPT; s++) {
        r[s] = base + t + TPB * s;
        ok[s] = (r[s] < NVOX);
    }

    unsigned long long acc[RPT][4];
#pragma unroll
    for (int s = 0; s < RPT; s++)
#pragma unroll
        for (int q = 0; q < 4; q++) acc[s][q] = 0ull;

    int jA[RPT], jB[RPT];
    float4 A0[RPT], B0[RPT], A1[RPT], B1[RPT];

    // Coalesced tap-major index fetch.
#define LOAD_IDX(k, J)                                           \
    {                                                            \
        const int* np = nbrT + (k) * NVOX;                       \
        _Pragma("unroll")                                        \
        for (int s = 0; s < RPT; s++)                            \
            J[s] = ok[s] ? __ldg(np + r[s]) : -1;                \
    }

#define LOAD_DATA(J, A, B)                                       \
    {                                                            \
        _Pragma("unroll")                                        \
        for (int s = 0; s < RPT; s++) {                          \
            A[s] = make_float4(0.f, 0.f, 0.f, 0.f);              \
            B[s] = A[s];                                         \
            if (J[s] >= 0) {                                     \
                A[s] = __ldg(x + J[s] * 2);                      \
                B[s] = __ldg(x + J[s] * 2 + 1);                  \
            }                                                    \
        }                                                        \
    }

#define FMA_TAP(k, A, B)                                                    \
    {                                                                       \
        const unsigned long long* wk = sw + (k) * 32;                       \
        _Pragma("unroll")                                                   \
        for (int c = 0; c < 8; c++) {                                       \
            const ulonglong2 wA = *(const ulonglong2*)(wk + c * 4);         \
            const ulonglong2 wB = *(const ulonglong2*)(wk + c * 4 + 2);     \
            _Pragma("unroll")                                               \
            for (int s = 0; s < RPT; s++) {                                 \
                float f;                                                    \
                switch (c) {                                                \
                    case 0: f = A[s].x; break;                              \
                    case 1: f = A[s].y; break;                              \
                    case 2: f = A[s].z; break;                              \
                    case 3: f = A[s].w; break;                              \
                    case 4: f = B[s].x; break;                              \
                    case 5: f = B[s].y; break;                              \
                    case 6: f = B[s].z; break;                              \
                    default: f = B[s].w; break;                             \
                }                                                           \
                const unsigned long long p = pack2(f);                      \
                ffma2(acc[s][0], p, wA.x);                                  \
                ffma2(acc[s][1], p, wA.y);                                  \
                ffma2(acc[s][2], p, wB.x);                                  \
                ffma2(acc[s][3], p, wB.y);                                  \
            }                                                               \
        }                                                                   \
    }

    // Pipeline: indices 2 taps ahead, gather data 1 tap ahead.
    LOAD_IDX(0, jA);
    LOAD_IDX(1, jB);
    LOAD_DATA(jA, A0, B0);            // tap 0 data in flight

#pragma unroll 1
    for (int k = 0; k < 26; k += 2) {
        LOAD_DATA(jB, A1, B1);        // tap k+1 data in flight
        if (k + 2 < KT) LOAD_IDX(k + 2, jA);
        FMA_TAP(k, A0, B0);
        if (k + 2 < KT) LOAD_DATA(jA, A0, B0);   // tap k+2 data in flight
        if (k + 3 < KT) LOAD_IDX(k + 3, jB);
        FMA_TAP(k + 1, A1, B1);
    }
    FMA_TAP(26, A0, B0);

    // Epilogue
#pragma unroll
    for (int s = 0; s < RPT; s++) {
        if (!ok[s]) continue;
        float v[8];
#pragma unroll
        for (int i = 0; i < 4; i++) {
            unsigned int lo, hi;
            asm("mov.b64 {%0, %1}, %2;" : "=r"(lo), "=r"(hi) : "l"(acc[s][i]));
            v[2 * i]     = __uint_as_float(lo);
            v[2 * i + 1] = __uint_as_float(hi);
        }
        if (RES) {
            const float4 ra = resid[r[s] * 2];
            const float4 rb = resid[r[s] * 2 + 1];
            v[0] += ra.x; v[1] += ra.y; v[2] += ra.z; v[3] += ra.w;
            v[4] += rb.x; v[5] += rb.y; v[6] += rb.z; v[7] += rb.w;
        }
        if (RELU) {
#pragma unroll
            for (int i = 0; i < 8; i++) v[i] = fmaxf(v[i], 0.f);
        }
        out[r[s] * 2]     = make_float4(v[0], v[1], v[2], v[3]);
        out[r[s] * 2 + 1] = make_float4(v[4], v[5], v[6], v[7]);
    }
#undef LOAD_IDX
#undef LOAD_DATA
#undef FMA_TAP
}

extern "C" void kernel_launch(void* const* d_in, const int* in_sizes, int n_in,
                              void* d_out, int out_size) {
    (void)in_sizes; (void)n_in; (void)out_size;
    const float* feats0 = (const float*)d_in[0];
    const float* feats1 = (const float*)d_in[1];
    const float* W0     = (const float*)d_in[2];  // [3][27][8][8]
    const float* W1     = (const float*)d_in[3];
    const int*   nbr0   = (const int*)d_in[4];    // [N][27]
    const int*   nbr1   = (const int*)d_in[5];
    float* out = (float*)d_out;

    float *bufA, *bufB;
    int *nT0, *nT1;
    cudaGetSymbolAddress((void**)&bufA, g_bufA);
    cudaGetSymbolAddress((void**)&bufB, g_bufB);
    cudaGetSymbolAddress((void**)&nT0, g_nbrT0);
    cudaGetSymbolAddress((void**)&nT1, g_nbrT1);

    const int tgrid = (NVOX + 255) / 256;
    transpose_nbr<<<tgrid, 256>>>(nbr0, nT0);
    transpose_nbr<<<tgrid, 256>>>(nbr1, nT1);

    const int grid = (NVOX + RPB - 1) / RPB;
    const int LW = KT * CH * CH;  // 1728 floats per layer

    // Grid 0
    spconv_kernel<true,  false><<<grid, TPB>>>((const float4*)feats0, nT0, W0,          nullptr,               (float4*)bufA);
    spconv_kernel<true,  false><<<grid, TPB>>>((const float4*)bufA,   nT0, W0 + LW,     nullptr,               (float4*)bufB);
    spconv_kernel<false, true ><<<grid, TPB>>>((const float4*)bufB,   nT0, W0 + 2 * LW, (const float4*)feats0, (float4*)out);
    // Grid 1
    spconv_kernel<true,  false><<<grid, TPB>>>((const float4*)feats1, nT1, W1,          nullptr,               (float4*)bufA);
    spconv_kernel<true,  false><<<grid, TPB>>>((const float4*)bufA,   nT1, W1 + LW,     nullptr,               (float4*)bufB);
    spconv_kernel<false, true ><<<grid, TPB>>>((const float4*)bufB,   nT1, W1 + 2 * LW, (const float4*)feats1, (float4*)out + NVOX * 2);
}

// round 5
// speedup vs baseline: 2.1156x; 2.1156x over previous
#include <cuda_runtime.h>

#define NVOX 500000
#define CH 8
#define KT 27
#define TPB 128
#define RPT 4                      // rows per thread
#define RPB (TPB * RPT)            // 512 rows per block
#define KCH 9                      // taps per smem chunk (3 chunks of 9)

// Ping-pong scratch for intermediate activations (16 MB each).
__device__ float g_bufA[NVOX * CH];
__device__ float g_bufB[NVOX * CH];

__device__ __forceinline__ void ffma2(unsigned long long& d,
                                      unsigned long long a,
                                      unsigned long long b) {
    asm volatile("fma.rn.f32x2 %0, %1, %2, %0;" : "+l"(d) : "l"(a), "l"(b));
}

__device__ __forceinline__ unsigned long long pack2(float x) {
    unsigned long long r;
    unsigned int xb = __float_as_uint(x);
    asm("mov.b64 %0, {%1, %1};" : "=l"(r) : "r"(xb));
    return r;
}

template <bool RELU, bool RES>
__global__ void __launch_bounds__(TPB, 5)
spconv_kernel(const float4* __restrict__ x,      // [NVOX][2] float4
              const int*    __restrict__ nbr,    // [NVOX][27] row-major
              const float*  __restrict__ w,      // [27][8][8]
              const float4* __restrict__ resid,  // [NVOX][2] or null
              float4*       __restrict__ out)    // [NVOX][2]
{
    // Weights as f32x2 pairs: sw[k*32 + cin*4 + p] = (w[k][cin][2p], w[k][cin][2p+1])
    __shared__ __align__(16) unsigned long long sw[KT * 32];   // 6912 B
    __shared__ __align__(16) int snbr[RPB * KCH];              // 18432 B

    {
        const unsigned long long* w2 = (const unsigned long long*)w;
        for (int i = threadIdx.x; i < KT * 32; i += TPB) sw[i] = w2[i];
    }

    const int t = threadIdx.x;
    const int base = blockIdx.x * RPB;
    const int rows = min(RPB, NVOX - base);

    int r[RPT]; bool ok[RPT];
#pragma unroll
    for (int s = 0; s < RPT; s++) {
        r[s] = base + t + TPB * s;
        ok[s] = (r[s] < NVOX);
    }

    unsigned long long acc[RPT][4];
#pragma unroll
    for (int s = 0; s < RPT; s++)
#pragma unroll
        for (int q = 0; q < 4; q++) acc[s][q] = 0ull;

    float4 A0[RPT], B0[RPT], A1[RPT], B1[RPT];
    int j[RPT];

#define LOAD_DATA(J, A, B)                                       \
    {                                                            \
        _Pragma("unroll")                                        \
        for (int s = 0; s < RPT; s++) {                          \
            A[s] = make_float4(0.f, 0.f, 0.f, 0.f);              \
            B[s] = A[s];                                         \
            if (J[s] >= 0) {                                     \
                A[s] = __ldg(x + J[s] * 2);                      \
                B[s] = __ldg(x + J[s] * 2 + 1);                  \
            }                                                    \
        }                                                        \
    }

#define LOAD_IDX(u, J)                                           \
    {                                                            \
        _Pragma("unroll")                                        \
        for (int s = 0; s < RPT; s++)                            \
            J[s] = ok[s] ? snbr[(t + TPB * s) * KCH + (u)] : -1; \
    }

#define FMA_TAP(k, A, B)                                                    \
    {                                                                       \
        const unsigned long long* wk = sw + (k) * 32;                       \
        _Pragma("unroll")                                                   \
        for (int c = 0; c < 8; c++) {                                       \
            const ulonglong2 wA = *(const ulonglong2*)(wk + c * 4);         \
            const ulonglong2 wB = *(const ulonglong2*)(wk + c * 4 + 2);     \
            _Pragma("unroll")                                               \
            for (int s = 0; s < RPT; s++) {                                 \
                float f;                                                    \
                switch (c) {                                                \
                    case 0: f = A[s].x; break;                              \
                    case 1: f = A[s].y; break;                              \
                    case 2: f = A[s].z; break;                              \
                    case 3: f = A[s].w; break;                              \
                    case 4: f = B[s].x; break;                              \
                    case 5: f = B[s].y; break;                              \
                    case 6: f = B[s].z; break;                              \
                    default: f = B[s].w; break;                             \
                }                                                           \
                const unsigned long long p = pack2(f);                      \
                ffma2(acc[s][0], p, wA.x);                                  \
                ffma2(acc[s][1], p, wA.y);                                  \
                ffma2(acc[s][2], p, wB.x);                                  \
                ffma2(acc[s][3], p, wB.y);                                  \
            }                                                               \
        }                                                                   \
    }

    const int* src = nbr + (long long)base * KT;

#pragma unroll 1
    for (int g = 0; g < 3; g++) {
        const int kbase = g * KCH;
        __syncthreads();   // also covers weight staging on g==0
        {
            const int tot = rows * KCH;
            for (int i = t; i < tot; i += TPB) {
                const int row = i / KCH;
                const int kk = i - row * KCH;
                snbr[i] = src[row * KT + kbase + kk];
            }
        }
        __syncthreads();

        // 2-deep gather pipeline over the 9 taps of this chunk.
        LOAD_IDX(0, j);
        LOAD_DATA(j, A0, B0);
#pragma unroll
        for (int u = 0; u < KCH - 1; u++) {
            LOAD_IDX(u + 1, j);
            if (u & 1) {
                LOAD_DATA(j, A0, B0);
                FMA_TAP(kbase + u, A1, B1);
            } else {
                LOAD_DATA(j, A1, B1);
                FMA_TAP(kbase + u, A0, B0);
            }
        }
        FMA_TAP(kbase + KCH - 1, A0, B0);   // tap 8 data sits in A0/B0
    }

    // Epilogue
#pragma unroll
    for (int s = 0; s < RPT; s++) {
        if (!ok[s]) continue;
        float v[8];
#pragma unroll
        for (int i = 0; i < 4; i++) {
            unsigned int lo, hi;
            asm("mov.b64 {%0, %1}, %2;" : "=r"(lo), "=r"(hi) : "l"(acc[s][i]));
            v[2 * i]     = __uint_as_float(lo);
            v[2 * i + 1] = __uint_as_float(hi);
        }
        if (RES) {
            const float4 ra = resid[r[s] * 2];
            const float4 rb = resid[r[s] * 2 + 1];
            v[0] += ra.x; v[1] += ra.y; v[2] += ra.z; v[3] += ra.w;
            v[4] += rb.x; v[5] += rb.y; v[6] += rb.z; v[7] += rb.w;
        }
        if (RELU) {
#pragma unroll
            for (int i = 0; i < 8; i++) v[i] = fmaxf(v[i], 0.f);
        }
        out[r[s] * 2]     = make_float4(v[0], v[1], v[2], v[3]);
        out[r[s] * 2 + 1] = make_float4(v[4], v[5], v[6], v[7]);
    }
#undef LOAD_DATA
#undef LOAD_IDX
#undef FMA_TAP
}

extern "C" void kernel_launch(void* const* d_in, const int* in_sizes, int n_in,
                              void* d_out, int out_size) {
    (void)in_sizes; (void)n_in; (void)out_size;
    const float* feats0 = (const float*)d_in[0];
    const float* feats1 = (const float*)d_in[1];
    const float* W0     = (const float*)d_in[2];  // [3][27][8][8]
    const float* W1     = (const float*)d_in[3];
    const int*   nbr0   = (const int*)d_in[4];    // [N][27]
    const int*   nbr1   = (const int*)d_in[5];
    float* out = (float*)d_out;

    float *bufA, *bufB;
    cudaGetSymbolAddress((void**)&bufA, g_bufA);
    cudaGetSymbolAddress((void**)&bufB, g_bufB);

    const int grid = (NVOX + RPB - 1) / RPB;
    const int LW = KT * CH * CH;  // 1728 floats per layer

    // Grid 0
    spconv_kernel<true,  false><<<grid, TPB>>>((const float4*)feats0, nbr0, W0,          nullptr,               (float4*)bufA);
    spconv_kernel<true,  false><<<grid, TPB>>>((const float4*)bufA,   nbr0, W0 + LW,     nullptr,               (float4*)bufB);
    spconv_kernel<false, true ><<<grid, TPB>>>((const float4*)bufB,   nbr0, W0 + 2 * LW, (const float4*)feats0, (float4*)out);
    // Grid 1
    spconv_kernel<true,  false><<<grid, TPB>>>((const float4*)feats1, nbr1, W1,          nullptr,               (float4*)bufA);
    spconv_kernel<true,  false><<<grid, TPB>>>((const float4*)bufA,   nbr1, W1 + LW,     nullptr,               (float4*)bufB);
    spconv_kernel<false, true ><<<grid, TPB>>>((const float4*)bufB,   nbr1, W1 + 2 * LW, (const float4*)feats1, (float4*)out + NVOX * 2);
}